// round 10
// baseline (speedup 1.0000x reference)
#include <cuda_runtime.h>

// Leapfrog (KDK), softened point mass: a = -q / (r*(r+1)^2 + 1e-12).
//
// v10 = v7 (scalar 2N threads, block=64/2048 CTAs, rsqrt-only MUFU, full
// unroll, dt = x*2^-6) + momentum rescaling to slim the saturated FFMA pipe
// (~96% busy at the measured ~1.1GHz effective clock):
//   P := dt * p  =>  drift:  q += P            (3 FADD, off the FFMA chain)
//                    kick:   P += (-dt^2/den)*q (3 FFMA, -dt^2 precomputed)
//   den = fma(2.0f, r2, t) keeps an immediate multiplier -> FFMA-imm rt=1.
// p recovered once at the end: p = P * (1/dt).
//
// Inputs: d_in[0]=ts f32[N], d_in[1]=w0_lead f32[N,6], d_in[2]=w0_trail f32[N,6],
//         d_in[3]=n_steps i32. Output f32[2N,6]: row 2i=trail_i, 2i+1=lead_i.

__device__ __forceinline__ float rsqrt_ap(float x) {
    float r; asm("rsqrt.approx.f32 %0, %1;" : "=f"(r) : "f"(x)); return r;
}

// P += ncoef * (-accel-direction): sc = -ncoef/den folded; ncoef = dt^2 or dt^2/2,
// passed pre-negated. 11 fma-pipe ops (one imm-form) + 2 MUFU.
__device__ __forceinline__ void kick(float& qx, float& qy, float& qz,
                                     float& Px, float& Py, float& Pz,
                                     float ncoef) {
    float r2  = fmaf(qx, qx, fmaf(qy, qy, qz * qz));
    float u   = rsqrt_ap(r2);            // 1/r
    float r   = r2 * u;                  // r
    float t   = fmaf(r, r2, r);          // r*r2 + r
    float den = fmaf(2.0f, r2, t);       // r(1+r)^2   (imm multiplier)
    float inv = rsqrt_ap(den * den);     // 1/den (den > 0)
    float sc  = inv * ncoef;             // -coef/den
    Px = fmaf(sc, qx, Px);
    Py = fmaf(sc, qy, Py);
    Pz = fmaf(sc, qz, Pz);
}

template <int INTERIOR, bool FULL_UNROLL>
__device__ __forceinline__ void integrate(float& qx, float& qy, float& qz,
                                          float& Px, float& Py, float& Pz,
                                          float dt, int interior_rt) {
    float dt2  = dt * dt;
    float ndt2 = -dt2;
    float nh2  = -0.5f * dt2;

    kick(qx, qy, qz, Px, Py, Pz, nh2);
    if (FULL_UNROLL) {
        #pragma unroll
        for (int s = 0; s < INTERIOR; ++s) {
            qx += Px; qy += Py; qz += Pz;          // drift: plain FADD
            kick(qx, qy, qz, Px, Py, Pz, ndt2);
        }
    } else {
        #pragma unroll 4
        for (int s = 0; s < interior_rt; ++s) {
            qx += Px; qy += Py; qz += Pz;
            kick(qx, qy, qz, Px, Py, Pz, ndt2);
        }
    }
    qx += Px; qy += Py; qz += Pz;
    kick(qx, qy, qz, Px, Py, Pz, nh2);
}

__global__ void __launch_bounds__(64)
leapfrog_v10_kernel(const float* __restrict__ ts,
                    const float* __restrict__ w0_lead,
                    const float* __restrict__ w0_trail,
                    const int*   __restrict__ n_steps_ptr,
                    float* __restrict__ out,
                    int N) {
    int tid = blockIdx.x * blockDim.x + threadIdx.x;
    if (tid >= 2 * N) return;

    int b = (tid >= N) ? 1 : 0;        // 0 = trail, 1 = lead
    int i = tid - b * N;

    const float* __restrict__ w0 = b ? w0_lead : w0_trail;

    int n_steps = *n_steps_ptr;
    float t_f = ts[N - 1] + 0.001f;    // broadcast, L2-resident

    const float2* __restrict__ row = reinterpret_cast<const float2*>(w0 + 6 * i);
    float2 v0 = row[0];
    float2 v1 = row[1];
    float2 v2 = row[2];
    float qx = v0.x, qy = v0.y, qz = v1.x;
    float px = v1.y, py = v2.x, pz = v2.y;

    float dt;
    if (n_steps == 64) {
        dt = (t_f - ts[i]) * 0.015625f;   // exact /64
    } else {
        dt = (t_f - ts[i]) / (float)n_steps;
    }

    // Rescale momentum: P = dt * p.
    float Px = dt * px, Py = dt * py, Pz = dt * pz;

    if (n_steps == 64) {
        integrate<63, true>(qx, qy, qz, Px, Py, Pz, dt, 63);
    } else {
        integrate<0, false>(qx, qy, qz, Px, Py, Pz, dt, n_steps - 1);
    }

    // Recover p = P / dt (IEEE div once, outside the hot loop).
    float inv_dt = 1.0f / dt;
    px = Px * inv_dt; py = Py * inv_dt; pz = Pz * inv_dt;

    int orow = 2 * i + b;
    float2* __restrict__ orow_p = reinterpret_cast<float2*>(out + 6 * orow);
    orow_p[0] = make_float2(qx, qy);
    orow_p[1] = make_float2(qz, px);
    orow_p[2] = make_float2(py, pz);
}

extern "C" void kernel_launch(void* const* d_in, const int* in_sizes, int n_in,
                              void* d_out, int out_size) {
    const float* ts       = (const float*)d_in[0];
    const float* w0_lead  = (const float*)d_in[1];
    const float* w0_trail = (const float*)d_in[2];
    const int*   n_steps  = (const int*)d_in[3];
    float* out = (float*)d_out;

    int N = in_sizes[0];
    int total = 2 * N;
    int threads = 64;                   // 2048 CTAs -> balanced 13-14 per SM
    int blocks = (total + threads - 1) / threads;
    leapfrog_v10_kernel<<<blocks, threads>>>(ts, w0_lead, w0_trail, n_steps, out, N);
}